// round 6
// baseline (speedup 1.0000x reference)
#include <cuda_runtime.h>
#include <cuda_fp16.h>
#include <cstdint>

// ---------------------------------------------------------------------------
// GCN 2-layer. R6: tf32 tensor GEMM -> fp16 message buffer -> CSR gather.
// ---------------------------------------------------------------------------

#define N_MAX 100000
#define E_MAX 1600000
#define F_DIM 128
#define NB_MAX 512

__device__ __half g_Ah[(size_t)N_MAX * F_DIM];   // GEMM output (fp16 messages)
__device__ float  g_B[(size_t)N_MAX * F_DIM];    // aggregated layer-1 output
__device__ float  g_deg[N_MAX];
__device__ float  g_dinv[N_MAX];
__device__ int    g_cnt[N_MAX];
__device__ int    g_off[N_MAX];
__device__ int    g_rowptr[N_MAX];
__device__ int    g_cursor[N_MAX];
__device__ int    g_bsum[NB_MAX];
__device__ int    g_bscan[NB_MAX];
__device__ int    g_csrc[E_MAX];
__device__ float  g_cnorm[E_MAX];
__device__ int    g_is64;

// --- int64 vs int32 edge_index detection ---
__global__ void k_detect(const unsigned* __restrict__ w) {
    __shared__ unsigned s;
    if (threadIdx.x == 0) s = 0u;
    __syncthreads();
    unsigned v = 0;
    for (int i = threadIdx.x; i < 4096; i += blockDim.x) v |= w[2 * i + 1];
    if (v) atomicOr(&s, 1u);
    __syncthreads();
    if (threadIdx.x == 0) g_is64 = (s == 0u) ? 1 : 0;
}

__device__ __forceinline__ void edge_decode(const void* ei, int E, int e,
                                            int& s, int& d) {
    if (g_is64) {
        const long long* p = (const long long*)ei;
        s = (int)p[e];
        d = (int)p[(size_t)E + e];
    } else {
        const int* p = (const int*)ei;
        s = p[e];
        d = p[(size_t)E + e];
    }
}

__global__ void k_initdeg(int N) {
    int i = blockIdx.x * blockDim.x + threadIdx.x;
    if (i < N) { g_deg[i] = 1.0f; g_cnt[i] = 0; }
}

__global__ void k_deg(const void* __restrict__ ei, const float* __restrict__ w, int E) {
    int e = blockIdx.x * blockDim.x + threadIdx.x;
    if (e >= E) return;
    int s, d;
    edge_decode(ei, E, e, s, d);
    atomicAdd(&g_deg[d], w[e]);
    atomicAdd(&g_cnt[d], 1);
}

__global__ void k_dinv(int N) {
    int i = blockIdx.x * blockDim.x + threadIdx.x;
    if (i >= N) return;
    float dg = g_deg[i];
    g_dinv[i] = (dg > 0.0f) ? rsqrtf(dg) : 0.0f;
}

// --- 2-level exclusive scan ---
__global__ void k_scan1(int N) {
    __shared__ int sh[256];
    int t = threadIdx.x;
    int i = blockIdx.x * 256 + t;
    int v = (i < N) ? g_cnt[i] : 0;
    sh[t] = v;
    __syncthreads();
#pragma unroll
    for (int off = 1; off < 256; off <<= 1) {
        int a = (t >= off) ? sh[t - off] : 0;
        __syncthreads();
        sh[t] += a;
        __syncthreads();
    }
    if (i < N) g_off[i] = sh[t] - v;
    if (t == 255) g_bsum[blockIdx.x] = sh[255];
}

__global__ void k_scan2(int NB) {
    __shared__ int sh[NB_MAX];
    int t = threadIdx.x;
    int v = (t < NB) ? g_bsum[t] : 0;
    sh[t] = v;
    __syncthreads();
#pragma unroll
    for (int off = 1; off < NB_MAX; off <<= 1) {
        int a = (t >= off) ? sh[t - off] : 0;
        __syncthreads();
        sh[t] += a;
        __syncthreads();
    }
    if (t < NB) g_bscan[t] = sh[t] - v;
}

__global__ void k_scan3(int N) {
    int i = blockIdx.x * blockDim.x + threadIdx.x;
    if (i >= N) return;
    int rp = g_off[i] + g_bscan[i >> 8];
    g_rowptr[i] = rp;
    g_cursor[i] = rp;
}

__global__ void k_fill(const void* __restrict__ ei, const float* __restrict__ w, int E) {
    int e = blockIdx.x * blockDim.x + threadIdx.x;
    if (e >= E) return;
    int s, d;
    edge_decode(ei, E, e, s, d);
    int pos = atomicAdd(&g_cursor[d], 1);
    g_csrc[pos] = s;
    g_cnorm[pos] = g_dinv[s] * w[e] * g_dinv[d];
}

// ---------------------------------------------------------------------------
// tf32 tensor-core GEMM: Ch[M,128] = act(X[M,K]) @ W[K,128]  (fp16 output)
// BM=128, BN=128, BK=32; 256 threads (8 warps).
// ---------------------------------------------------------------------------
#define SMSTRIDE 40

__device__ __forceinline__ unsigned f2tf(float f) {
    unsigned r;
    asm("cvt.rna.tf32.f32 %0, %1;" : "=r"(r) : "f"(f));
    return r;
}
__device__ __forceinline__ void ldsm4(unsigned& r0, unsigned& r1,
                                      unsigned& r2, unsigned& r3, unsigned a) {
    asm volatile("ldmatrix.sync.aligned.m8n8.x4.shared.b16 {%0,%1,%2,%3}, [%4];"
                 : "=r"(r0), "=r"(r1), "=r"(r2), "=r"(r3) : "r"(a));
}
__device__ __forceinline__ void ldsm2(unsigned& r0, unsigned& r1, unsigned a) {
    asm volatile("ldmatrix.sync.aligned.m8n8.x2.shared.b16 {%0,%1}, [%2];"
                 : "=r"(r0), "=r"(r1) : "r"(a));
}
__device__ __forceinline__ void mma_tf32(float* c, const unsigned* a, const unsigned* b) {
    asm volatile(
        "mma.sync.aligned.m16n8k8.row.col.f32.tf32.tf32.f32 "
        "{%0,%1,%2,%3}, {%4,%5,%6,%7}, {%8,%9}, {%0,%1,%2,%3};"
        : "+f"(c[0]), "+f"(c[1]), "+f"(c[2]), "+f"(c[3])
        : "r"(a[0]), "r"(a[1]), "r"(a[2]), "r"(a[3]), "r"(b[0]), "r"(b[1]));
}

template <bool RELU>
__global__ __launch_bounds__(256) void k_tgemm(
    const float* __restrict__ X, const float* __restrict__ W,
    __half* __restrict__ Ch, int M, int K)
{
    __shared__ __align__(128) unsigned As[128 * SMSTRIDE];
    __shared__ __align__(128) unsigned Bs[128 * SMSTRIDE];

    const int tid = threadIdx.x;
    const int lane = tid & 31;
    const int wid = tid >> 5;
    const int warp_m = wid & 1;
    const int warp_n = wid >> 1;
    const int rowBase = blockIdx.x * 128;

    const unsigned sA = (unsigned)__cvta_generic_to_shared(As);
    const unsigned sB = (unsigned)__cvta_generic_to_shared(Bs);

    const int aRowL = ((lane >> 3) & 1) * 8 + (lane & 7);
    const int aColS = (lane >> 4) * 16;
    const unsigned swzA = ((unsigned)(aRowL & 4)) << 2;
    const int bRowL = lane & 7;
    const int bColS = ((lane >> 3) & 1) * 16;
    const unsigned swzB = ((unsigned)(bRowL & 4)) << 2;

    unsigned aBase[4], bBase[4];
#pragma unroll
    for (int mt = 0; mt < 4; mt++)
        aBase[mt] = sA + ((warp_m * 64 + mt * 16 + aRowL) * SMSTRIDE) * 4 + aColS;
#pragma unroll
    for (int nt = 0; nt < 4; nt++)
        bBase[nt] = sB + ((warp_n * 32 + nt * 8 + bRowL) * SMSTRIDE) * 4 + bColS;

    float acc[4][4][4];
#pragma unroll
    for (int i = 0; i < 4; i++)
#pragma unroll
        for (int j = 0; j < 4; j++)
#pragma unroll
            for (int v = 0; v < 4; v++) acc[i][j][v] = 0.0f;

    for (int k0 = 0; k0 < K; k0 += 32) {
#pragma unroll
        for (int it = 0; it < 4; it++) {
            int idx = it * 256 + tid;
            int row = idx >> 3;
            int c4 = idx & 7;
            float4 xv = make_float4(0.f, 0.f, 0.f, 0.f);
            int gr = rowBase + row;
            if (gr < M) xv = *(const float4*)(X + (size_t)gr * K + k0 + c4 * 4);
            if (RELU) {
                xv.x = fmaxf(xv.x, 0.f); xv.y = fmaxf(xv.y, 0.f);
                xv.z = fmaxf(xv.z, 0.f); xv.w = fmaxf(xv.w, 0.f);
            }
            uint4 tv = make_uint4(f2tf(xv.x), f2tf(xv.y), f2tf(xv.z), f2tf(xv.w));
            unsigned boff = row * SMSTRIDE * 4 + ((c4 * 16) ^ (((unsigned)(row & 4)) << 2));
            *(uint4*)((char*)As + boff) = tv;
        }
#pragma unroll
        for (int it = 0; it < 4; it++) {
            int idx = it * 256 + tid;
            int kr = idx >> 5;
            int n4 = idx & 31;
            float4 wv = *(const float4*)(W + (size_t)(k0 + kr) * 128 + n4 * 4);
            unsigned t0 = f2tf(wv.x), t1 = f2tf(wv.y), t2 = f2tf(wv.z), t3 = f2tf(wv.w);
            int r0 = n4 * 4;
#pragma unroll
            for (int j = 0; j < 4; j++) {
                unsigned tj = (j == 0) ? t0 : (j == 1) ? t1 : (j == 2) ? t2 : t3;
                int row = r0 + j;
                unsigned boff = row * SMSTRIDE * 4 + ((kr * 4) ^ (((unsigned)(row & 4)) << 2));
                *(unsigned*)((char*)Bs + boff) = tj;
            }
        }
        __syncthreads();

#pragma unroll
        for (int ks = 0; ks < 4; ks++) {
            unsigned afrag[4][4], bfrag[4][2];
#pragma unroll
            for (int mt = 0; mt < 4; mt++)
                ldsm4(afrag[mt][0], afrag[mt][1], afrag[mt][2], afrag[mt][3],
                      (aBase[mt] + ks * 32) ^ swzA);
#pragma unroll
            for (int nt = 0; nt < 4; nt++)
                ldsm2(bfrag[nt][0], bfrag[nt][1], (bBase[nt] + ks * 32) ^ swzB);
#pragma unroll
            for (int mt = 0; mt < 4; mt++)
#pragma unroll
                for (int nt = 0; nt < 4; nt++)
                    mma_tf32(acc[mt][nt], afrag[mt], bfrag[nt]);
        }
        __syncthreads();
    }

    // --- epilogue: fp16 store ---
    const int crow = lane >> 2;
    const int ccol = (lane & 3) * 2;
#pragma unroll
    for (int mt = 0; mt < 4; mt++) {
        int r0 = rowBase + warp_m * 64 + mt * 16 + crow;
#pragma unroll
        for (int nt = 0; nt < 4; nt++) {
            int col = warp_n * 32 + nt * 8 + ccol;
            if (r0 < M) {
                __half2 h = __floats2half2_rn(acc[mt][nt][0], acc[mt][nt][1]);
                *(__half2*)(Ch + (size_t)r0 * 128 + col) = h;
            }
            if (r0 + 8 < M) {
                __half2 h = __floats2half2_rn(acc[mt][nt][2], acc[mt][nt][3]);
                *(__half2*)(Ch + (size_t)(r0 + 8) * 128 + col) = h;
            }
        }
    }
}

// ---------------------------------------------------------------------------
// CSR gather (fp16 messages): one warp per dst; lane owns 4 features (8B).
// ---------------------------------------------------------------------------
__global__ __launch_bounds__(256) void k_gather(
    const __half* __restrict__ lin, const float* __restrict__ bias,
    float* __restrict__ out, int N)
{
    int warp = (blockIdx.x * blockDim.x + threadIdx.x) >> 5;
    if (warp >= N) return;
    int lane = threadIdx.x & 31;
    int d = warp;

    float di = g_dinv[d];
    float s = di * di;
    float4 b4 = ((const float4*)bias)[lane];

    const __half2* lh = (const __half2*)lin;
    size_t self = (size_t)d * 64 + lane * 2;
    float2 v0 = __half22float2(lh[self]);
    float2 v1 = __half22float2(lh[self + 1]);
    float4 acc = make_float4(fmaf(v0.x, s, b4.x), fmaf(v0.y, s, b4.y),
                             fmaf(v1.x, s, b4.z), fmaf(v1.y, s, b4.w));

    int beg = g_rowptr[d];
    int end = beg + g_cnt[d];
    int e = beg;
    for (; e + 1 < end; e += 2) {
        int s0 = g_csrc[e];     float n0 = g_cnorm[e];
        int s1 = g_csrc[e + 1]; float n1 = g_cnorm[e + 1];
        uint2 p0 = ((const uint2*)lin)[(size_t)s0 * 32 + lane];
        uint2 p1 = ((const uint2*)lin)[(size_t)s1 * 32 + lane];
        float2 a0 = __half22float2(*(const __half2*)&p0.x);
        float2 a1 = __half22float2(*(const __half2*)&p0.y);
        float2 c0 = __half22float2(*(const __half2*)&p1.x);
        float2 c1 = __half22float2(*(const __half2*)&p1.y);
        acc.x = fmaf(a0.x, n0, acc.x); acc.y = fmaf(a0.y, n0, acc.y);
        acc.z = fmaf(a1.x, n0, acc.z); acc.w = fmaf(a1.y, n0, acc.w);
        acc.x = fmaf(c0.x, n1, acc.x); acc.y = fmaf(c0.y, n1, acc.y);
        acc.z = fmaf(c1.x, n1, acc.z); acc.w = fmaf(c1.y, n1, acc.w);
    }
    if (e < end) {
        int s0 = g_csrc[e]; float n0 = g_cnorm[e];
        uint2 p0 = ((const uint2*)lin)[(size_t)s0 * 32 + lane];
        float2 a0 = __half22float2(*(const __half2*)&p0.x);
        float2 a1 = __half22float2(*(const __half2*)&p0.y);
        acc.x = fmaf(a0.x, n0, acc.x); acc.y = fmaf(a0.y, n0, acc.y);
        acc.z = fmaf(a1.x, n0, acc.z); acc.w = fmaf(a1.y, n0, acc.w);
    }
    ((float4*)out)[(size_t)d * 32 + lane] = acc;
}

// ---------------------------------------------------------------------------

static inline int cdiv(long long a, long long b) { return (int)((a + b - 1) / b); }

extern "C" void kernel_launch(void* const* d_in, const int* in_sizes, int n_in,
                              void* d_out, int out_size)
{
    const float* x   = (const float*)d_in[0];
    const void*  ei  = d_in[1];
    const float* ew  = (const float*)d_in[2];
    const float* W1  = (const float*)d_in[3];
    const float* b1  = (const float*)d_in[4];
    const float* W2  = (const float*)d_in[5];
    const float* b2  = (const float*)d_in[6];
    float* out = (float*)d_out;

    const int HID = in_sizes[4];                 // 128
    const int K1  = in_sizes[3] / HID;           // 256
    const int N   = in_sizes[0] / K1;            // 100000
    const int E   = in_sizes[2];                 // 1600000

    __half* Ah; float* B;
    cudaGetSymbolAddress((void**)&Ah, g_Ah);
    cudaGetSymbolAddress((void**)&B, g_B);

    const int T = 256;
    const int NB = cdiv(N, 256);

    // --- graph normalization + CSR build ---
    k_detect<<<1, T>>>((const unsigned*)ei);
    k_initdeg<<<cdiv(N, T), T>>>(N);
    k_deg<<<cdiv(E, T), T>>>(ei, ew, E);
    k_dinv<<<cdiv(N, T), T>>>(N);
    k_scan1<<<NB, 256>>>(N);
    k_scan2<<<1, NB_MAX>>>(NB);
    k_scan3<<<cdiv(N, T), T>>>(N);
    k_fill<<<cdiv(E, T), T>>>(ei, ew, E);

    // --- layer 1 ---
    k_tgemm<false><<<cdiv(N, 128), T>>>(x, W1, Ah, N, K1);
    k_gather<<<cdiv((long long)N * 32, T), T>>>(Ah, b1, B, N);

    // --- layer 2 ---
    k_tgemm<true><<<cdiv(N, 128), T>>>(B, W2, Ah, N, HID);
    k_gather<<<cdiv((long long)N * 32, T), T>>>(Ah, b2, out, N);
}

// round 7
// speedup vs baseline: 1.4686x; 1.4686x over previous
#include <cuda_runtime.h>
#include <cstdint>

// ---------------------------------------------------------------------------
// GCN 2-layer. R7: R5 pipeline (tf32 MMA + fp32 CSR gather) +
//   stream fork-join overlap of CSR build with GEMM1, fused setup kernels,
//   unroll-4 gather.
// ---------------------------------------------------------------------------

#define N_MAX 100000
#define E_MAX 1600000
#define F_DIM 128
#define NB_MAX 512

__device__ float g_A[(size_t)N_MAX * F_DIM];
__device__ float g_B[(size_t)N_MAX * F_DIM];
__device__ float g_deg[N_MAX];
__device__ float g_dinv[N_MAX];
__device__ int   g_cnt[N_MAX];
__device__ int   g_off[N_MAX];
__device__ int   g_rowptr[N_MAX];
__device__ int   g_cursor[N_MAX];
__device__ int   g_bsum[NB_MAX];
__device__ int   g_bscan[NB_MAX];
__device__ int   g_csrc[E_MAX];
__device__ float g_cnorm[E_MAX];
__device__ int   g_is64;

// --- fused: int64/int32 detection (block 0) + deg/cnt init (all blocks) ---
__global__ void k_setup(const unsigned* __restrict__ w, int N) {
    int i = blockIdx.x * blockDim.x + threadIdx.x;
    if (i < N) { g_deg[i] = 1.0f; g_cnt[i] = 0; }
    if (blockIdx.x == 0) {
        __shared__ unsigned s;
        if (threadIdx.x == 0) s = 0u;
        __syncthreads();
        unsigned v = 0;
        for (int j = threadIdx.x; j < 4096; j += blockDim.x) v |= w[2 * j + 1];
        if (v) atomicOr(&s, 1u);
        __syncthreads();
        if (threadIdx.x == 0) g_is64 = (s == 0u) ? 1 : 0;
    }
}

__device__ __forceinline__ void edge_decode(const void* ei, int E, int e,
                                            int& s, int& d) {
    if (g_is64) {
        const long long* p = (const long long*)ei;
        s = (int)p[e];
        d = (int)p[(size_t)E + e];
    } else {
        const int* p = (const int*)ei;
        s = p[e];
        d = p[(size_t)E + e];
    }
}

__global__ void k_deg(const void* __restrict__ ei, const float* __restrict__ w, int E) {
    int e = blockIdx.x * blockDim.x + threadIdx.x;
    if (e >= E) return;
    int s, d;
    edge_decode(ei, E, e, s, d);
    atomicAdd(&g_deg[d], w[e]);
    atomicAdd(&g_cnt[d], 1);
}

// --- scan1 + fused dinv ---
__global__ void k_scan1(int N) {
    __shared__ int sh[256];
    int t = threadIdx.x;
    int i = blockIdx.x * 256 + t;
    if (i < N) {
        float dg = g_deg[i];
        g_dinv[i] = (dg > 0.0f) ? rsqrtf(dg) : 0.0f;
    }
    int v = (i < N) ? g_cnt[i] : 0;
    sh[t] = v;
    __syncthreads();
#pragma unroll
    for (int off = 1; off < 256; off <<= 1) {
        int a = (t >= off) ? sh[t - off] : 0;
        __syncthreads();
        sh[t] += a;
        __syncthreads();
    }
    if (i < N) g_off[i] = sh[t] - v;
    if (t == 255) g_bsum[blockIdx.x] = sh[255];
}

__global__ void k_scan2(int NB) {
    __shared__ int sh[NB_MAX];
    int t = threadIdx.x;
    int v = (t < NB) ? g_bsum[t] : 0;
    sh[t] = v;
    __syncthreads();
#pragma unroll
    for (int off = 1; off < NB_MAX; off <<= 1) {
        int a = (t >= off) ? sh[t - off] : 0;
        __syncthreads();
        sh[t] += a;
        __syncthreads();
    }
    if (t < NB) g_bscan[t] = sh[t] - v;
}

__global__ void k_scan3(int N) {
    int i = blockIdx.x * blockDim.x + threadIdx.x;
    if (i >= N) return;
    int rp = g_off[i] + g_bscan[i >> 8];
    g_rowptr[i] = rp;
    g_cursor[i] = rp;
}

__global__ void k_fill(const void* __restrict__ ei, const float* __restrict__ w, int E) {
    int e = blockIdx.x * blockDim.x + threadIdx.x;
    if (e >= E) return;
    int s, d;
    edge_decode(ei, E, e, s, d);
    int pos = atomicAdd(&g_cursor[d], 1);
    g_csrc[pos] = s;
    g_cnorm[pos] = g_dinv[s] * w[e] * g_dinv[d];
}

// ---------------------------------------------------------------------------
// tf32 tensor-core GEMM (R5-proven): C[M,128] = act(X[M,K]) @ W[K,128]
// ---------------------------------------------------------------------------
#define SMSTRIDE 40

__device__ __forceinline__ unsigned f2tf(float f) {
    unsigned r;
    asm("cvt.rna.tf32.f32 %0, %1;" : "=r"(r) : "f"(f));
    return r;
}
__device__ __forceinline__ void ldsm4(unsigned& r0, unsigned& r1,
                                      unsigned& r2, unsigned& r3, unsigned a) {
    asm volatile("ldmatrix.sync.aligned.m8n8.x4.shared.b16 {%0,%1,%2,%3}, [%4];"
                 : "=r"(r0), "=r"(r1), "=r"(r2), "=r"(r3) : "r"(a));
}
__device__ __forceinline__ void ldsm2(unsigned& r0, unsigned& r1, unsigned a) {
    asm volatile("ldmatrix.sync.aligned.m8n8.x2.shared.b16 {%0,%1}, [%2];"
                 : "=r"(r0), "=r"(r1) : "r"(a));
}
__device__ __forceinline__ void mma_tf32(float* c, const unsigned* a, const unsigned* b) {
    asm volatile(
        "mma.sync.aligned.m16n8k8.row.col.f32.tf32.tf32.f32 "
        "{%0,%1,%2,%3}, {%4,%5,%6,%7}, {%8,%9}, {%0,%1,%2,%3};"
        : "+f"(c[0]), "+f"(c[1]), "+f"(c[2]), "+f"(c[3])
        : "r"(a[0]), "r"(a[1]), "r"(a[2]), "r"(a[3]), "r"(b[0]), "r"(b[1]));
}

template <bool RELU>
__global__ __launch_bounds__(256) void k_tgemm(
    const float* __restrict__ X, const float* __restrict__ W,
    float* __restrict__ C, int M, int K)
{
    __shared__ __align__(128) unsigned As[128 * SMSTRIDE];
    __shared__ __align__(128) unsigned Bs[128 * SMSTRIDE];

    const int tid = threadIdx.x;
    const int lane = tid & 31;
    const int wid = tid >> 5;
    const int warp_m = wid & 1;
    const int warp_n = wid >> 1;
    const int rowBase = blockIdx.x * 128;

    const unsigned sA = (unsigned)__cvta_generic_to_shared(As);
    const unsigned sB = (unsigned)__cvta_generic_to_shared(Bs);

    const int aRowL = ((lane >> 3) & 1) * 8 + (lane & 7);
    const int aColS = (lane >> 4) * 16;
    const unsigned swzA = ((unsigned)(aRowL & 4)) << 2;
    const int bRowL = lane & 7;
    const int bColS = ((lane >> 3) & 1) * 16;
    const unsigned swzB = ((unsigned)(bRowL & 4)) << 2;

    unsigned aBase[4], bBase[4];
#pragma unroll
    for (int mt = 0; mt < 4; mt++)
        aBase[mt] = sA + ((warp_m * 64 + mt * 16 + aRowL) * SMSTRIDE) * 4 + aColS;
#pragma unroll
    for (int nt = 0; nt < 4; nt++)
        bBase[nt] = sB + ((warp_n * 32 + nt * 8 + bRowL) * SMSTRIDE) * 4 + bColS;

    float acc[4][4][4];
#pragma unroll
    for (int i = 0; i < 4; i++)
#pragma unroll
        for (int j = 0; j < 4; j++)
#pragma unroll
            for (int v = 0; v < 4; v++) acc[i][j][v] = 0.0f;

    for (int k0 = 0; k0 < K; k0 += 32) {
#pragma unroll
        for (int it = 0; it < 4; it++) {
            int idx = it * 256 + tid;
            int row = idx >> 3;
            int c4 = idx & 7;
            float4 xv = make_float4(0.f, 0.f, 0.f, 0.f);
            int gr = rowBase + row;
            if (gr < M) xv = *(const float4*)(X + (size_t)gr * K + k0 + c4 * 4);
            if (RELU) {
                xv.x = fmaxf(xv.x, 0.f); xv.y = fmaxf(xv.y, 0.f);
                xv.z = fmaxf(xv.z, 0.f); xv.w = fmaxf(xv.w, 0.f);
            }
            uint4 tv = make_uint4(f2tf(xv.x), f2tf(xv.y), f2tf(xv.z), f2tf(xv.w));
            unsigned boff = row * SMSTRIDE * 4 + ((c4 * 16) ^ (((unsigned)(row & 4)) << 2));
            *(uint4*)((char*)As + boff) = tv;
        }
#pragma unroll
        for (int it = 0; it < 4; it++) {
            int idx = it * 256 + tid;
            int kr = idx >> 5;
            int n4 = idx & 31;
            float4 wv = *(const float4*)(W + (size_t)(k0 + kr) * 128 + n4 * 4);
            unsigned t0 = f2tf(wv.x), t1 = f2tf(wv.y), t2 = f2tf(wv.z), t3 = f2tf(wv.w);
            int r0 = n4 * 4;
#pragma unroll
            for (int j = 0; j < 4; j++) {
                unsigned tj = (j == 0) ? t0 : (j == 1) ? t1 : (j == 2) ? t2 : t3;
                int row = r0 + j;
                unsigned boff = row * SMSTRIDE * 4 + ((kr * 4) ^ (((unsigned)(row & 4)) << 2));
                *(unsigned*)((char*)Bs + boff) = tj;
            }
        }
        __syncthreads();

#pragma unroll
        for (int ks = 0; ks < 4; ks++) {
            unsigned afrag[4][4], bfrag[4][2];
#pragma unroll
            for (int mt = 0; mt < 4; mt++)
                ldsm4(afrag[mt][0], afrag[mt][1], afrag[mt][2], afrag[mt][3],
                      (aBase[mt] + ks * 32) ^ swzA);
#pragma unroll
            for (int nt = 0; nt < 4; nt++)
                ldsm2(bfrag[nt][0], bfrag[nt][1], (bBase[nt] + ks * 32) ^ swzB);
#pragma unroll
            for (int mt = 0; mt < 4; mt++)
#pragma unroll
                for (int nt = 0; nt < 4; nt++)
                    mma_tf32(acc[mt][nt], afrag[mt], bfrag[nt]);
        }
        __syncthreads();
    }

    const int crow = lane >> 2;
    const int ccol = (lane & 3) * 2;
#pragma unroll
    for (int mt = 0; mt < 4; mt++) {
        int r0 = rowBase + warp_m * 64 + mt * 16 + crow;
#pragma unroll
        for (int nt = 0; nt < 4; nt++) {
            int col = warp_n * 32 + nt * 8 + ccol;
            if (r0 < M) {
                float2 v = make_float2(acc[mt][nt][0], acc[mt][nt][1]);
                *(float2*)(C + (size_t)r0 * 128 + col) = v;
            }
            if (r0 + 8 < M) {
                float2 v = make_float2(acc[mt][nt][2], acc[mt][nt][3]);
                *(float2*)(C + (size_t)(r0 + 8) * 128 + col) = v;
            }
        }
    }
}

// ---------------------------------------------------------------------------
// CSR gather: one warp per dst node, unroll-4 for MLP.
// ---------------------------------------------------------------------------
__global__ __launch_bounds__(256) void k_gather(
    const float* __restrict__ lin, const float* __restrict__ bias,
    float* __restrict__ out, int N)
{
    int warp = (blockIdx.x * blockDim.x + threadIdx.x) >> 5;
    if (warp >= N) return;
    int lane = threadIdx.x & 31;
    int d = warp;

    float di = g_dinv[d];
    float s = di * di;
    float4 b4 = ((const float4*)bias)[lane];
    float4 v = ((const float4*)lin)[(size_t)d * 32 + lane];
    float4 acc = make_float4(fmaf(v.x, s, b4.x), fmaf(v.y, s, b4.y),
                             fmaf(v.z, s, b4.z), fmaf(v.w, s, b4.w));

    int beg = g_rowptr[d];
    int end = beg + g_cnt[d];
    int e = beg;
    for (; e + 3 < end; e += 4) {
        int s0 = g_csrc[e];     float n0 = g_cnorm[e];
        int s1 = g_csrc[e + 1]; float n1 = g_cnorm[e + 1];
        int s2 = g_csrc[e + 2]; float n2 = g_cnorm[e + 2];
        int s3 = g_csrc[e + 3]; float n3 = g_cnorm[e + 3];
        float4 u0 = ((const float4*)lin)[(size_t)s0 * 32 + lane];
        float4 u1 = ((const float4*)lin)[(size_t)s1 * 32 + lane];
        float4 u2 = ((const float4*)lin)[(size_t)s2 * 32 + lane];
        float4 u3 = ((const float4*)lin)[(size_t)s3 * 32 + lane];
        acc.x = fmaf(u0.x, n0, acc.x); acc.y = fmaf(u0.y, n0, acc.y);
        acc.z = fmaf(u0.z, n0, acc.z); acc.w = fmaf(u0.w, n0, acc.w);
        acc.x = fmaf(u1.x, n1, acc.x); acc.y = fmaf(u1.y, n1, acc.y);
        acc.z = fmaf(u1.z, n1, acc.z); acc.w = fmaf(u1.w, n1, acc.w);
        acc.x = fmaf(u2.x, n2, acc.x); acc.y = fmaf(u2.y, n2, acc.y);
        acc.z = fmaf(u2.z, n2, acc.z); acc.w = fmaf(u2.w, n2, acc.w);
        acc.x = fmaf(u3.x, n3, acc.x); acc.y = fmaf(u3.y, n3, acc.y);
        acc.z = fmaf(u3.z, n3, acc.z); acc.w = fmaf(u3.w, n3, acc.w);
    }
    for (; e < end; e++) {
        int s0 = g_csrc[e]; float n0 = g_cnorm[e];
        float4 u0 = ((const float4*)lin)[(size_t)s0 * 32 + lane];
        acc.x = fmaf(u0.x, n0, acc.x); acc.y = fmaf(u0.y, n0, acc.y);
        acc.z = fmaf(u0.z, n0, acc.z); acc.w = fmaf(u0.w, n0, acc.w);
    }
    ((float4*)out)[(size_t)d * 32 + lane] = acc;
}

// ---------------------------------------------------------------------------

static inline int cdiv(long long a, long long b) { return (int)((a + b - 1) / b); }

extern "C" void kernel_launch(void* const* d_in, const int* in_sizes, int n_in,
                              void* d_out, int out_size)
{
    const float* x   = (const float*)d_in[0];
    const void*  ei  = d_in[1];
    const float* ew  = (const float*)d_in[2];
    const float* W1  = (const float*)d_in[3];
    const float* b1  = (const float*)d_in[4];
    const float* W2  = (const float*)d_in[5];
    const float* b2  = (const float*)d_in[6];
    float* out = (float*)d_out;

    const int HID = in_sizes[4];                 // 128
    const int K1  = in_sizes[3] / HID;           // 256
    const int N   = in_sizes[0] / K1;            // 100000
    const int E   = in_sizes[2];                 // 1600000

    float* A; float* B;
    cudaGetSymbolAddress((void**)&A, g_A);
    cudaGetSymbolAddress((void**)&B, g_B);

    const int T = 256;
    const int NB = cdiv(N, 256);

    // Fork: CSR build on side stream, GEMM1 on main stream (both captured).
    cudaStream_t side;
    cudaStreamCreateWithFlags(&side, cudaStreamNonBlocking);
    cudaEvent_t evFork, evJoin;
    cudaEventCreateWithFlags(&evFork, cudaEventDisableTiming);
    cudaEventCreateWithFlags(&evJoin, cudaEventDisableTiming);

    cudaEventRecord(evFork, 0);
    cudaStreamWaitEvent(side, evFork, 0);

    // --- side stream: graph normalization + CSR build ---
    k_setup<<<cdiv(N, T), T, 0, side>>>((const unsigned*)ei, N);
    k_deg<<<cdiv(E, T), T, 0, side>>>(ei, ew, E);
    k_scan1<<<NB, 256, 0, side>>>(N);
    k_scan2<<<1, NB_MAX, 0, side>>>(NB);
    k_scan3<<<cdiv(N, T), T, 0, side>>>(N);
    k_fill<<<cdiv(E, T), T, 0, side>>>(ei, ew, E);
    cudaEventRecord(evJoin, side);

    // --- main stream: layer-1 GEMM (independent of CSR) ---
    k_tgemm<false><<<cdiv(N, 128), T>>>(x, W1, A, N, K1);

    // Join, then the dependent chain.
    cudaStreamWaitEvent(0, evJoin, 0);
    k_gather<<<cdiv((long long)N * 32, T), T>>>(A, b1, B, N);

    k_tgemm<true><<<cdiv(N, 128), T>>>(B, W2, A, N, HID);
    k_gather<<<cdiv((long long)N * 32, T), T>>>(A, b2, out, N);
}